// round 7
// baseline (speedup 1.0000x reference)
#include <cuda_runtime.h>

// ---------------------------------------------------------------------------
// LSTM_10522669875315 — fp32 SIMT baseline with algorithmic restructuring:
//  * token->xproj lookup table (VOCAB=10, EMBED=10)
//  * gate-interleaved recurrent weight matrix (row 4u+gate) so the c/h
//    update is local to the GEMM tile owner
//  * 256 step-kernels in the captured graph, double-buffered h
//  * packed f32x2 FMA (FFMA2) inner loop: 128 MACs/cyc/SM
// ---------------------------------------------------------------------------

#define BATCH 256
#define SEQT  256
#define HID   1024
#define G4H   4096
#define EMB   10
#define NVOC  10
#define NCLS  10

// Device-global scratch (allocation-free rule: __device__ arrays)
__device__ float g_Wr[G4H * HID];          // 16 MB: interleaved recurrent weights
__device__ float g_xt[NVOC * G4H];         // 160 KB: per-token projected gate bias table
__device__ float g_h[2][BATCH * HID];      // double-buffered hidden state
__device__ float g_c[BATCH * HID];         // cell state (exclusive ownership per elem)
__device__ int   g_xflag;                  // 1 if tokens are int64, 0 if int32

// ---------------------------------------------------------------------------
// f32x2 packed helpers (FFMA2 only reachable via PTX fma.rn.f32x2)
// ---------------------------------------------------------------------------
typedef unsigned long long u64;

__device__ __forceinline__ u64 pk2(float x, float y) {
    u64 r;
    asm("mov.b64 %0, {%1, %2};" : "=l"(r) : "f"(x), "f"(y));
    return r;
}
__device__ __forceinline__ void upk2(u64 v, float& x, float& y) {
    asm("mov.b64 {%0, %1}, %2;" : "=f"(x), "=f"(y) : "l"(v));
}
__device__ __forceinline__ u64 ffma2(u64 a, u64 b, u64 c) {
    u64 d;
    asm("fma.rn.f32x2 %0, %1, %2, %3;" : "=l"(d) : "l"(a), "l"(b), "l"(c));
    return d;
}

// ---------------------------------------------------------------------------
// Detect token dtype: int64 little-endian 0..9 => every odd 32-bit word is 0.
// (For actual int32 tokens, 32 consecutive odd slots all being 0 has
//  probability 1e-32 — effectively impossible.)
// ---------------------------------------------------------------------------
__global__ void k_detect(const int* x32) {
    if (threadIdx.x == 0) {
        int f = 1;
        for (int i = 1; i < 64; i += 2)
            if (x32[i] != 0) f = 0;
        g_xflag = f;
    }
}

// Zero h[0] and c. 512 blocks x 256 threads, one float4 each.
__global__ void k_init() {
    int id = blockIdx.x * blockDim.x + threadIdx.x;   // 0..131071
    float4 z = make_float4(0.f, 0.f, 0.f, 0.f);
    if (id < (BATCH * HID / 4)) {
        ((float4*)g_h[0])[id] = z;
    } else {
        ((float4*)g_c)[id - (BATCH * HID / 4)] = z;
    }
}

// xtable[v][4u+g] = b_g[u] + sum_e embed[v][e] * W_gx[u][e]  (gate-interleaved)
__global__ void k_prep(const float* __restrict__ embed,
                       const float* __restrict__ Wg, const float* __restrict__ Wi,
                       const float* __restrict__ Wf, const float* __restrict__ Wo,
                       const float* __restrict__ bg, const float* __restrict__ bi,
                       const float* __restrict__ bfp, const float* __restrict__ bo) {
    int id = blockIdx.x * 256 + threadIdx.x;          // 0..40959
    int v   = id >> 12;                               // vocab index
    int col = id & (G4H - 1);
    int u   = col >> 2;
    int gi  = col & 3;
    const float* W  = (gi == 0) ? Wg : (gi == 1) ? Wi : (gi == 2) ? Wf : Wo;
    const float* bb = (gi == 0) ? bg : (gi == 1) ? bi : (gi == 2) ? bfp : bo;
    float s = bb[u];
#pragma unroll
    for (int e = 0; e < EMB; e++)
        s += embed[v * EMB + e] * W[u * EMB + e];
    g_xt[id] = s;
}

// Interleave recurrent weights: g_Wr[4u+gate][k] = W_gate_h[u][k]
__global__ void k_reorder(const float* __restrict__ Wg, const float* __restrict__ Wi,
                          const float* __restrict__ Wf, const float* __restrict__ Wo) {
    int r  = blockIdx.x;                              // 0..4095
    int u  = r >> 2;
    int gi = r & 3;
    const float* W = (gi == 0) ? Wg : (gi == 1) ? Wi : (gi == 2) ? Wf : Wo;
    float4 v = ((const float4*)(W + u * HID))[threadIdx.x];
    ((float4*)(g_Wr + r * HID))[threadIdx.x] = v;
}

// ---------------------------------------------------------------------------
// One timestep: z = h_in @ Wr^T (+ xtable[token]), gates, c/h update.
// Grid: (64, 2)  -> N-slice of 64 z-cols (16 hidden units) x M-tile of 128 rows.
// Block: 256 threads, thread (tx,ty): tx in 0..15 owns one hidden unit
// (4 consecutive z columns), ty in 0..15 owns 8 batch rows (ty + 16*i).
// ---------------------------------------------------------------------------
#define SA 36                                         // As row stride (pad)
#define BADDR(k, n) ((k) * 68 + (n) + (((n) & 32) >> 4))

__global__ void __launch_bounds__(256, 1) k_step(const void* __restrict__ xin, int t) {
    __shared__ float As[128 * SA];                    // 18 KB
    __shared__ float Bs[32 * 68 + 8];                 // ~8.7 KB, column-gap swizzle

    const float* __restrict__ hin  = g_h[t & 1];
    float* __restrict__       hout = g_h[(t + 1) & 1];

    int tid = threadIdx.x;
    int tx = tid & 15, ty = tid >> 4;
    int m0   = blockIdx.y * 128;
    int u0   = blockIdx.x * 16;
    int col0 = u0 * 4;

    u64 acc[8][2];
#pragma unroll
    for (int i = 0; i < 8; i++) { acc[i][0] = 0ULL; acc[i][1] = 0ULL; }

    for (int kc = 0; kc < HID; kc += 32) {
        __syncthreads();
        // Fill A tile: 128 rows x 32 k  (coalesced float4 loads of h)
#pragma unroll
        for (int q = 0; q < 4; q++) {
            int lin = tid + q * 256;                  // 0..1023 float4s
            int row = lin >> 3, kq = lin & 7;
            float4 v = *(const float4*)&hin[(m0 + row) * HID + kc + kq * 4];
            *(float4*)&As[row * SA + kq * 4] = v;
        }
        // Fill B tile: 64 n x 32 k, stored k-major with bank-gap swizzle
#pragma unroll
        for (int q = 0; q < 2; q++) {
            int lin = tid + q * 256;                  // 0..511 float4s
            int n = lin >> 3, kq = lin & 7;
            float4 v = *(const float4*)&g_Wr[(col0 + n) * HID + kc + kq * 4];
            int k4 = kq * 4;
            Bs[BADDR(k4 + 0, n)] = v.x;
            Bs[BADDR(k4 + 1, n)] = v.y;
            Bs[BADDR(k4 + 2, n)] = v.z;
            Bs[BADDR(k4 + 3, n)] = v.w;
        }
        __syncthreads();

#pragma unroll
        for (int kk = 0; kk < 32; kk += 2) {
            u64 b00 = *(const u64*)&Bs[BADDR(kk,     tx * 4)];
            u64 b01 = *(const u64*)&Bs[BADDR(kk,     tx * 4 + 2)];
            u64 b10 = *(const u64*)&Bs[BADDR(kk + 1, tx * 4)];
            u64 b11 = *(const u64*)&Bs[BADDR(kk + 1, tx * 4 + 2)];
#pragma unroll
            for (int i = 0; i < 8; i++) {
                float2 av = *(const float2*)&As[(ty + 16 * i) * SA + kk];
                u64 a0 = pk2(av.x, av.x);
                u64 a1 = pk2(av.y, av.y);
                acc[i][0] = ffma2(a0, b00, acc[i][0]);
                acc[i][1] = ffma2(a0, b01, acc[i][1]);
                acc[i][0] = ffma2(a1, b10, acc[i][0]);
                acc[i][1] = ffma2(a1, b11, acc[i][1]);
            }
        }
    }

    // Fused epilogue: add token projection, gates, update c and h.
    const long long* x64 = (const long long*)xin;
    const int*       x32 = (const int*)xin;
    int xf = g_xflag;
    int u = u0 + tx;
#pragma unroll
    for (int i = 0; i < 8; i++) {
        int m = m0 + ty + 16 * i;
        int v = xf ? (int)x64[m * SEQT + t] : x32[m * SEQT + t];
        float4 xt = *(const float4*)&g_xt[v * G4H + 4 * u];
        float z0, z1, z2, z3;
        upk2(acc[i][0], z0, z1);
        upk2(acc[i][1], z2, z3);
        float gg = tanhf(z0 + xt.x);
        float ii = 1.f / (1.f + expf(-(z1 + xt.y)));
        float ff = 1.f / (1.f + expf(-(z2 + xt.z)));
        float oo = 1.f / (1.f + expf(-(z3 + xt.w)));
        int idx = m * HID + u;
        float c = gg * ii + g_c[idx] * ff;
        g_c[idx] = c;
        hout[idx] = tanhf(c) * oo;
    }
}

// Final projection: y = h_T @ W_ph^T + b_p   (256 x 10)
__global__ void k_out(const float* __restrict__ Wp, const float* __restrict__ bp,
                      float* __restrict__ out) {
    __shared__ float s[NCLS * 128];
    int b = blockIdx.x, tid = threadIdx.x;            // 128 threads
    const float* h = g_h[0] + b * HID;                // last write was t=255 -> buf 0
    float acc[NCLS];
#pragma unroll
    for (int c = 0; c < NCLS; c++) acc[c] = 0.f;
    for (int k = tid; k < HID; k += 128) {
        float hv = h[k];
#pragma unroll
        for (int c = 0; c < NCLS; c++) acc[c] += hv * Wp[c * HID + k];
    }
#pragma unroll
    for (int c = 0; c < NCLS; c++) s[c * 128 + tid] = acc[c];
    __syncthreads();
    if (tid < NCLS) {
        float sum = bp[tid];
        for (int j = 0; j < 128; j++) sum += s[tid * 128 + j];
        out[b * NCLS + tid] = sum;
    }
}

// ---------------------------------------------------------------------------
// Inputs (metadata order): x, embed, W_gx, W_ix, W_fx, W_ox,
//   W_gh, W_ih, W_fh, W_oh, W_ph, b_g, b_i, b_f, b_o, b_p
// ---------------------------------------------------------------------------
extern "C" void kernel_launch(void* const* d_in, const int* in_sizes, int n_in,
                              void* d_out, int out_size) {
    (void)in_sizes; (void)n_in; (void)out_size;
    const void*  x     = d_in[0];
    const float* embed = (const float*)d_in[1];
    const float* Wgx   = (const float*)d_in[2];
    const float* Wix   = (const float*)d_in[3];
    const float* Wfx   = (const float*)d_in[4];
    const float* Wox   = (const float*)d_in[5];
    const float* Wgh   = (const float*)d_in[6];
    const float* Wih   = (const float*)d_in[7];
    const float* Wfh   = (const float*)d_in[8];
    const float* Woh   = (const float*)d_in[9];
    const float* Wph   = (const float*)d_in[10];
    const float* bg    = (const float*)d_in[11];
    const float* bi    = (const float*)d_in[12];
    const float* bfp   = (const float*)d_in[13];
    const float* bo    = (const float*)d_in[14];
    const float* bp    = (const float*)d_in[15];

    k_detect<<<1, 32>>>((const int*)x);
    k_init<<<512, 256>>>();
    k_prep<<<160, 256>>>(embed, Wgx, Wix, Wfx, Wox, bg, bi, bfp, bo);
    k_reorder<<<4096, 256>>>(Wgh, Wih, Wfh, Woh);

    for (int t = 0; t < SEQT; t++)
        k_step<<<dim3(64, 2), 256>>>(x, t);

    k_out<<<256, 128>>>(Wph, bp, (float*)d_out);
}